// round 1
// baseline (speedup 1.0000x reference)
#include <cuda_runtime.h>
#include <math.h>

#define L_SEQ   2048
#define D_IN    1024
#define N_ST    16
#define BATCH   2
#define NTOK    (BATCH * L_SEQ)      // 4096
#define NCHUNK  32
#define CLEN    64                   // L_SEQ / NCHUNK
#define LOG2E   1.4426950408889634f

// ------------------------------- scratch ----------------------------------
__device__ float g_delta[NTOK * D_IN];                     // (tok, d)  16 MB
__device__ float g_bc   [NTOK * 32];                       // (tok, n)  n<16:B, n>=16:C
__device__ float g_sd   [BATCH * D_IN * NCHUNK];           // sum of delta per chunk
__device__ float g_hloc [BATCH * D_IN * NCHUNK * N_ST];    // local end state per chunk
__device__ float g_hin  [BATCH * D_IN * NCHUNK * N_ST];    // carry-in per chunk

__device__ __forceinline__ float ex2f(float x) {
    float r; asm("ex2.approx.ftz.f32 %0, %1;" : "=f"(r) : "f"(x)); return r;
}

__device__ __forceinline__ float softplusf(float z) {
    return fmaxf(z, 0.0f) + log1pf(__expf(-fabsf(z)));
}

// ------------------------- K1: projections + delta -------------------------
// 128 blocks x 256 threads, 32 tokens per block.
// Stage 1: x_dbl[t][c] = sum_k x[t][k] * W1[c][k]       (c = 0..63)
// Stage 2: delta[t][d] = softplus(sum_r x_dbl[t][r] * dtW[d][r] + bias[d])
// Epilogue: B/C with gradient-guided C correction.
__global__ __launch_bounds__(256) void k1_proj(
    const float* __restrict__ x,      // (B,L,D)
    const float* __restrict__ w1,     // (64,1024)
    const float* __restrict__ dtw,    // (1024,32)
    const float* __restrict__ bias,   // (1024)
    const float* __restrict__ gs,     // (B,L)
    const float* __restrict__ gcw,    // (16)
    const float* __restrict__ gcb,    // (16)
    const float* __restrict__ gCw)    // scalar
{
    __shared__ union {
        struct { float sX[32][65]; float sW[64][65]; } a;
        struct { float sXd[32][65]; float sDW[128][33]; } b;
    } sm;

    const int tid = threadIdx.x;
    const int tokbase = blockIdx.x * 32;

    // ---- stage 1: 64-output projection, k-tiled ----
    const int kk = tid & 63, q = tid >> 6;           // coop-load coords
    const int ct = tid & 15, tt = tid >> 4;          // compute coords
    const int c0 = ct * 4, t0 = tt * 2;

    float acc[4][2];
#pragma unroll
    for (int i = 0; i < 4; i++) { acc[i][0] = 0.f; acc[i][1] = 0.f; }

    for (int kt = 0; kt < 16; kt++) {
        const int k0 = kt * 64;
#pragma unroll
        for (int r = 0; r < 8; r++) {
            int t = q + r * 4;
            sm.a.sX[t][kk] = x[(size_t)(tokbase + t) * D_IN + k0 + kk];
        }
#pragma unroll
        for (int r = 0; r < 16; r++) {
            int c = q + r * 4;
            sm.a.sW[c][kk] = w1[(size_t)c * D_IN + k0 + kk];
        }
        __syncthreads();
#pragma unroll 16
        for (int k2 = 0; k2 < 64; k2++) {
            float xv0 = sm.a.sX[t0][k2];
            float xv1 = sm.a.sX[t0 + 1][k2];
#pragma unroll
            for (int i = 0; i < 4; i++) {
                float wv = sm.a.sW[c0 + i][k2];
                acc[i][0] += wv * xv0;
                acc[i][1] += wv * xv1;
            }
        }
        __syncthreads();
    }

    // write x_dbl to smem (union: same bytes as sX)
#pragma unroll
    for (int i = 0; i < 4; i++) {
        sm.b.sXd[t0][c0 + i]     = acc[i][0];
        sm.b.sXd[t0 + 1][c0 + i] = acc[i][1];
    }
    __syncthreads();

    // ---- epilogue: B and corrected C ----
    {
        const float gCwv = gCw[0];
#pragma unroll
        for (int i = 0; i < 4; i++) {
            int idx = tid + i * 256;          // 0..1023 = 32 tok * 32 n
            int t = idx >> 5, n = idx & 31;
            float v = sm.b.sXd[t][32 + n];
            int tok = tokbase + t;
            int b = tok >> 11, l = tok & 2047;
            if (n >= 16) {
                int n2 = n - 16;
                float ge = gs[b * 2048 + n2 * 128 + (l >> 4)] * gcw[l & 15] + gcb[l & 15];
                v += gCwv * ge;
            }
            g_bc[(size_t)tok * 32 + n] = v;
        }
    }

    // ---- stage 2: delta ----
    const int dlane = tid & 127, th = tid >> 7;      // 2 token halves of 16
    for (int db = 0; db < 8; db++) {
        __syncthreads();
#pragma unroll
        for (int i = 0; i < 16; i++) {
            int idx = tid + i * 256;                 // 0..4095 = 128 d * 32 r
            sm.b.sDW[idx >> 5][idx & 31] =
                dtw[(size_t)(db * 128 + (idx >> 5)) * 32 + (idx & 31)];
        }
        __syncthreads();

        float w[32];
#pragma unroll
        for (int k = 0; k < 32; k++) w[k] = sm.b.sDW[dlane][k];
        const int d = db * 128 + dlane;
        const float bz = bias[d];

        for (int t = th * 16; t < th * 16 + 16; t++) {
            float a = bz;
#pragma unroll
            for (int k = 0; k < 32; k++) a += w[k] * sm.b.sXd[t][k];
            g_delta[(size_t)(tokbase + t) * D_IN + d] = softplusf(a);
        }
    }
}

// --------------------- K2: scan phase 1 (chunk summaries) ------------------
// grid 512 = B(2) * dgroups(8) * chunks(32); 128 threads = 128 d-channels.
__global__ __launch_bounds__(128) void k2_phase1(
    const float* __restrict__ x, const float* __restrict__ alogs)
{
    __shared__ float sB[CLEN][16];
    const int tid = threadIdx.x;
    const int bid = blockIdx.x;
    const int ch = bid & 31;
    const int dg = (bid >> 5) & 7;
    const int b  = bid >> 8;
    const int d  = dg * 128 + tid;
    const int l0 = ch * CLEN;

    // load B tile (first 16 of each 32-float bc row)
#pragma unroll
    for (int i = 0; i < 2; i++) {
        int idx = tid + i * 128;                 // 0..255
        int s = idx >> 2, q4 = idx & 3;
        float4 v = *(const float4*)&g_bc[(size_t)(b * 2048 + l0 + s) * 32 + q4 * 4];
        ((float4*)&sB[s][0])[q4] = v;
    }
    __syncthreads();

    float cn[16];
#pragma unroll
    for (int n = 0; n < 16; n++)
        cn[n] = -__expf(alogs[(size_t)d * 16 + n]) * LOG2E;
    bool fast = true;
#pragma unroll
    for (int n = 1; n < 16; n++) {
        float want = (float)(n + 1) * cn[0];
        fast = fast && (fabsf(cn[n] - want) <= 1e-4f * fabsf(want));
    }

    float h[16];
#pragma unroll
    for (int n = 0; n < 16; n++) h[n] = 0.f;
    float sd = 0.f;

    const float* dlt = &g_delta[(size_t)(b * 2048 + l0) * D_IN + d];
    const float* xp  = &x[(size_t)(b * 2048 + l0) * D_IN + d];

    if (fast) {
        const float c0 = cn[0];
        for (int s = 0; s < CLEN; s++) {
            float dv = dlt[(size_t)s * D_IN];
            float xv = xp[(size_t)s * D_IN];
            sd += dv;
            float e = ex2f(dv * c0);
            float u = dv * xv;
            float p = e;
#pragma unroll
            for (int n = 0; n < 16; n++) {
                h[n] = p * h[n] + u * sB[s][n];
                p *= e;
            }
        }
    } else {
        for (int s = 0; s < CLEN; s++) {
            float dv = dlt[(size_t)s * D_IN];
            float xv = xp[(size_t)s * D_IN];
            sd += dv;
            float u = dv * xv;
#pragma unroll
            for (int n = 0; n < 16; n++) {
                float a = ex2f(dv * cn[n]);
                h[n] = a * h[n] + u * sB[s][n];
            }
        }
    }

    const size_t base = (size_t)(b * 1024 + d) * NCHUNK + ch;
    g_sd[base] = sd;
#pragma unroll
    for (int n = 0; n < 16; n++) g_hloc[base * 16 + n] = h[n];
}

// ----------------------- K3: combine chunk carries -------------------------
// thread per (b,d,n): 32768 threads, sequential over 32 chunks.
__global__ __launch_bounds__(256) void k3_combine(const float* __restrict__ alogs)
{
    const int tid = blockIdx.x * 256 + threadIdx.x;      // 0..32767
    const int n = tid & 15;
    const int bd = tid >> 4;                             // b*1024 + d
    const int d = bd & 1023;
    const float cnf = -__expf(alogs[(size_t)d * 16 + n]) * LOG2E;

    float H = 0.f;
    const size_t base = (size_t)bd * NCHUNK;
    for (int c = 0; c < NCHUNK; c++) {
        g_hin[(base + c) * 16 + n] = H;
        float P = ex2f(g_sd[base + c] * cnf);
        H = P * H + g_hloc[(base + c) * 16 + n];
    }
}

// ----------------------- K4: scan phase 3 (emit y) --------------------------
__global__ __launch_bounds__(128) void k4_phase3(
    const float* __restrict__ x, const float* __restrict__ alogs,
    const float* __restrict__ Ds, float* __restrict__ y)
{
    __shared__ float sB[CLEN][16];
    __shared__ float sC[CLEN][16];
    const int tid = threadIdx.x;
    const int bid = blockIdx.x;
    const int ch = bid & 31;
    const int dg = (bid >> 5) & 7;
    const int b  = bid >> 8;
    const int d  = dg * 128 + tid;
    const int l0 = ch * CLEN;

#pragma unroll
    for (int i = 0; i < 4; i++) {
        int idx = tid + i * 128;                 // 0..511
        int s = idx >> 3, q8 = idx & 7;
        float4 v = *(const float4*)&g_bc[(size_t)(b * 2048 + l0 + s) * 32 + q8 * 4];
        if (q8 < 4) ((float4*)&sB[s][0])[q8] = v;
        else        ((float4*)&sC[s][0])[q8 - 4] = v;
    }
    __syncthreads();

    float cn[16];
#pragma unroll
    for (int n = 0; n < 16; n++)
        cn[n] = -__expf(alogs[(size_t)d * 16 + n]) * LOG2E;
    bool fast = true;
#pragma unroll
    for (int n = 1; n < 16; n++) {
        float want = (float)(n + 1) * cn[0];
        fast = fast && (fabsf(cn[n] - want) <= 1e-4f * fabsf(want));
    }

    const size_t base = (size_t)(b * 1024 + d) * NCHUNK + ch;
    float h[16];
#pragma unroll
    for (int n = 0; n < 16; n++) h[n] = g_hin[base * 16 + n];

    const float dsv = Ds[d];
    const float* dlt = &g_delta[(size_t)(b * 2048 + l0) * D_IN + d];
    const float* xp  = &x[(size_t)(b * 2048 + l0) * D_IN + d];
    float* yp        = &y[(size_t)(b * 2048 + l0) * D_IN + d];

    if (fast) {
        const float c0 = cn[0];
        for (int s = 0; s < CLEN; s++) {
            float dv = dlt[(size_t)s * D_IN];
            float xv = xp[(size_t)s * D_IN];
            float e = ex2f(dv * c0);
            float u = dv * xv;
            float p = e;
            float y0 = 0.f, y1 = 0.f, y2 = 0.f, y3 = 0.f;
#pragma unroll
            for (int n = 0; n < 16; n++) {
                h[n] = p * h[n] + u * sB[s][n];
                p *= e;
                float t = h[n] * sC[s][n];
                if ((n & 3) == 0) y0 += t;
                else if ((n & 3) == 1) y1 += t;
                else if ((n & 3) == 2) y2 += t;
                else y3 += t;
            }
            yp[(size_t)s * D_IN] = (y0 + y1) + (y2 + y3) + xv * dsv;
        }
    } else {
        for (int s = 0; s < CLEN; s++) {
            float dv = dlt[(size_t)s * D_IN];
            float xv = xp[(size_t)s * D_IN];
            float u = dv * xv;
            float y0 = 0.f, y1 = 0.f, y2 = 0.f, y3 = 0.f;
#pragma unroll
            for (int n = 0; n < 16; n++) {
                float a = ex2f(dv * cn[n]);
                h[n] = a * h[n] + u * sB[s][n];
                float t = h[n] * sC[s][n];
                if ((n & 3) == 0) y0 += t;
                else if ((n & 3) == 1) y1 += t;
                else if ((n & 3) == 2) y2 += t;
                else y3 += t;
            }
            yp[(size_t)s * D_IN] = (y0 + y1) + (y2 + y3) + xv * dsv;
        }
    }
}

// ------------------------------- launcher ----------------------------------
extern "C" void kernel_launch(void* const* d_in, const int* in_sizes, int n_in,
                              void* d_out, int out_size)
{
    const float* x     = (const float*)d_in[0];
    const float* gs    = (const float*)d_in[1];
    const float* w1    = (const float*)d_in[2];
    const float* dtw   = (const float*)d_in[3];
    const float* bias  = (const float*)d_in[4];
    const float* alogs = (const float*)d_in[5];
    const float* Ds    = (const float*)d_in[6];
    const float* gcw   = (const float*)d_in[7];
    const float* gcb   = (const float*)d_in[8];
    const float* gCw   = (const float*)d_in[9];
    float* y = (float*)d_out;

    k1_proj  <<<128, 256>>>(x, w1, dtw, bias, gs, gcw, gcb, gCw);
    k2_phase1<<<512, 128>>>(x, alogs);
    k3_combine<<<128, 256>>>(alogs);
    k4_phase3<<<512, 128>>>(x, alogs, Ds, y);
}